// round 2
// baseline (speedup 1.0000x reference)
#include <cuda_runtime.h>
#include <cuda_bf16.h>
#include <cstdint>

// Problem constants
#define M_ROWS 4096
#define K_DIM  256
#define NN     16384
#define KTOP   1638

// ---------------------------------------------------------------------------
// Scratch: CSC-compressed W.  layout: pair[slot][n] = (val, k-as-bits)
// Capacity 256 slots per column => can never overflow, exact for any input.
// ---------------------------------------------------------------------------
__device__ float2 g_pair[(size_t)K_DIM * NN];   // 32 MB
__device__ int    g_cnt[NN];

// ---------------------------------------------------------------------------
// Kernel 1: build CSC of W.  One thread per output column.
// Reads of W[k*NN + n] are coalesced across threads (adjacent n).
// Zero weights are dropped: never changes the sum.
// ---------------------------------------------------------------------------
__global__ void __launch_bounds__(128) build_csc_kernel(const float* __restrict__ W) {
    const int n = blockIdx.x * blockDim.x + threadIdx.x;
    if (n >= NN) return;
    int c = 0;
#pragma unroll 8
    for (int k = 0; k < K_DIM; ++k) {
        const float w = W[k * NN + n];
        if (w != 0.0f) {
            g_pair[(size_t)c * NN + n] = make_float2(w, __int_as_float(k));
            ++c;
        }
    }
    g_cnt[n] = c;
}

// ---------------------------------------------------------------------------
// Kernel 2: sparse GEMM  h = relu(x @ W + bias), written dense to out.
// Tile: 128 rows x 128 cols per block. 8 warps; each warp owns 16 columns
// sequentially; each lane owns 4 consecutive rows (float4 from smem x-tile).
// xs stride 132 (floats): main-loop LDS.128 conflict-free, fill 4-way only.
// os stride 129: column-stores 4-way, row-flush conflict-free + coalesced.
// ---------------------------------------------------------------------------
#define XS_STRIDE 132
#define OS_STRIDE 129
#define GEMM_SMEM ((K_DIM * XS_STRIDE + 128 * OS_STRIDE) * 4)

__global__ void __launch_bounds__(256, 1) gemm_kernel(
    const float* __restrict__ x,
    const float* __restrict__ bias,
    float* __restrict__ out)
{
    extern __shared__ float sm[];
    float* xs = sm;                       // [K_DIM][132]
    float* os = sm + K_DIM * XS_STRIDE;   // [128][129]

    const int row0 = blockIdx.y << 7;
    const int col0 = blockIdx.x << 7;

    // load x tile, transposed: xs[k][r]
    for (int l = threadIdx.x; l < 128 * K_DIM; l += 256) {
        const int r = l >> 8;        // 0..127
        const int k = l & 255;       // 0..255
        xs[k * XS_STRIDE + r] = x[(row0 + r) * K_DIM + k];
    }
    __syncthreads();

    const int warp  = threadIdx.x >> 5;
    const int lane  = threadIdx.x & 31;
    const int rbase = lane << 2;

    for (int cc = 0; cc < 16; ++cc) {
        const int c = (warp << 4) + cc;
        const int n = col0 + c;
        const int cnt = g_cnt[n];
        const float2* __restrict__ pp = g_pair + n;

        float4 acc = make_float4(0.f, 0.f, 0.f, 0.f);
        int j = 0;
        for (; j + 4 <= cnt; j += 4) {
            const float2 p0 = pp[(size_t)(j + 0) * NN];
            const float2 p1 = pp[(size_t)(j + 1) * NN];
            const float2 p2 = pp[(size_t)(j + 2) * NN];
            const float2 p3 = pp[(size_t)(j + 3) * NN];
            {
                const float4 xv = *(const float4*)(xs + __float_as_int(p0.y) * XS_STRIDE + rbase);
                acc.x = fmaf(xv.x, p0.x, acc.x); acc.y = fmaf(xv.y, p0.x, acc.y);
                acc.z = fmaf(xv.z, p0.x, acc.z); acc.w = fmaf(xv.w, p0.x, acc.w);
            }
            {
                const float4 xv = *(const float4*)(xs + __float_as_int(p1.y) * XS_STRIDE + rbase);
                acc.x = fmaf(xv.x, p1.x, acc.x); acc.y = fmaf(xv.y, p1.x, acc.y);
                acc.z = fmaf(xv.z, p1.x, acc.z); acc.w = fmaf(xv.w, p1.x, acc.w);
            }
            {
                const float4 xv = *(const float4*)(xs + __float_as_int(p2.y) * XS_STRIDE + rbase);
                acc.x = fmaf(xv.x, p2.x, acc.x); acc.y = fmaf(xv.y, p2.x, acc.y);
                acc.z = fmaf(xv.z, p2.x, acc.z); acc.w = fmaf(xv.w, p2.x, acc.w);
            }
            {
                const float4 xv = *(const float4*)(xs + __float_as_int(p3.y) * XS_STRIDE + rbase);
                acc.x = fmaf(xv.x, p3.x, acc.x); acc.y = fmaf(xv.y, p3.x, acc.y);
                acc.z = fmaf(xv.z, p3.x, acc.z); acc.w = fmaf(xv.w, p3.x, acc.w);
            }
        }
        for (; j < cnt; ++j) {
            const float2 p = pp[(size_t)j * NN];
            const float4 xv = *(const float4*)(xs + __float_as_int(p.y) * XS_STRIDE + rbase);
            acc.x = fmaf(xv.x, p.x, acc.x); acc.y = fmaf(xv.y, p.x, acc.y);
            acc.z = fmaf(xv.z, p.x, acc.z); acc.w = fmaf(xv.w, p.x, acc.w);
        }

        const float b = __ldg(bias + n);
        acc.x = fmaxf(acc.x + b, 0.f);
        acc.y = fmaxf(acc.y + b, 0.f);
        acc.z = fmaxf(acc.z + b, 0.f);
        acc.w = fmaxf(acc.w + b, 0.f);

        os[(rbase + 0) * OS_STRIDE + c] = acc.x;
        os[(rbase + 1) * OS_STRIDE + c] = acc.y;
        os[(rbase + 2) * OS_STRIDE + c] = acc.z;
        os[(rbase + 3) * OS_STRIDE + c] = acc.w;
    }
    __syncthreads();

    // flush tile, coalesced (consecutive threads -> consecutive columns)
    for (int l = threadIdx.x; l < 128 * 128; l += 256) {
        const int r = l >> 7;
        const int c = l & 127;
        out[(size_t)(row0 + r) * NN + col0 + c] = os[r * OS_STRIDE + c];
    }
}

// ---------------------------------------------------------------------------
// Kernel 3: per-row exact top-K (radix select on float bits; all values >= 0
// after relu so uint compare is order-preserving). In-place on `out`.
// Pass1 bits[31:23] warp-private hists; pass2 bits[22:12]; pass3 bits[11:0].
// Exact tie handling matching jax.lax.top_k (lowest index first).
// ---------------------------------------------------------------------------
#define SEL_SMEM (NN * 4 + 4096 * 4 + 512 * 4)

__global__ void __launch_bounds__(256) topk_kernel(float* __restrict__ out) {
    extern __shared__ unsigned int smv[];
    unsigned int* v    = smv;                       // [16384]
    int*          hist = (int*)(smv + NN);          // up to 4096 bins
    int*          eqix = (int*)(smv + NN + 4096);   // [512]

    __shared__ int chunksum[256];
    __shared__ int s_b1, s_b2, s_b3, s_krem, s_eqcnt;

    const int t = threadIdx.x;
    float* rp = out + (size_t)blockIdx.x * NN;

    // load row (vectorized)
    for (int i = t; i < NN / 4; i += 256)
        ((uint4*)v)[i] = ((const uint4*)rp)[i];

    // ---- pass 1: bits [31:23], per-warp private 256-bin histograms ----
    const int warp = t >> 5;
    for (int i = t; i < 8 * 256; i += 256) hist[i] = 0;
    __syncthreads();
    {
        int* h1 = hist + warp * 256;
        for (int i = t; i < NN; i += 256) atomicAdd(&h1[v[i] >> 23], 1);
    }
    __syncthreads();
    {
        int s = 0;
        for (int w = 0; w < 8; ++w) s += hist[w * 256 + t];
        chunksum[t] = s;   // total count of bin t
    }
    __syncthreads();
    if (t == 0) {
        int kr = KTOP;
        int b = 255;
        for (;; --b) { const int h = chunksum[b]; if (h >= kr) break; kr -= h; }
        s_b1 = b; s_krem = kr;
    }
    __syncthreads();
    const unsigned int b1 = (unsigned int)s_b1;

    // ---- pass 2: bits [22:12] (2048 bins) among prefix matches ----
    for (int i = t; i < 2048; i += 256) hist[i] = 0;
    __syncthreads();
    for (int i = t; i < NN; i += 256) {
        const unsigned int u = v[i];
        if ((u >> 23) == b1) atomicAdd(&hist[(u >> 12) & 2047], 1);
    }
    __syncthreads();
    { int s = 0; for (int k = 0; k < 8; ++k) s += hist[t * 8 + k]; chunksum[t] = s; }
    __syncthreads();
    if (t == 0) {
        int kr = s_krem;
        int c = 255;
        for (;; --c) { const int h = chunksum[c]; if (h >= kr) break; kr -= h; }
        int b = c * 8 + 7;
        for (;; --b) { const int h = hist[b]; if (h >= kr) break; kr -= h; }
        s_b2 = b; s_krem = kr;
    }
    __syncthreads();
    const unsigned int pfx2 = (b1 << 11) | (unsigned int)s_b2;

    // ---- pass 3: bits [11:0] (4096 bins) ----
    for (int i = t; i < 4096; i += 256) hist[i] = 0;
    __syncthreads();
    for (int i = t; i < NN; i += 256) {
        const unsigned int u = v[i];
        if ((u >> 12) == pfx2) atomicAdd(&hist[u & 4095], 1);
    }
    __syncthreads();
    { int s = 0; for (int k = 0; k < 16; ++k) s += hist[t * 16 + k]; chunksum[t] = s; }
    __syncthreads();
    if (t == 0) {
        int kr = s_krem;
        int c = 255;
        for (;; --c) { const int h = chunksum[c]; if (h >= kr) break; kr -= h; }
        int b = c * 16 + 15;
        for (;; --b) { const int h = hist[b]; if (h >= kr) break; kr -= h; }
        s_b3 = b; s_krem = kr;       // kr = how many elements == t to KEEP
        s_eqcnt = 0;
    }
    __syncthreads();

    const unsigned int tbits = (pfx2 << 12) | (unsigned int)s_b3;
    const int need = s_krem;         // 1 <= need <= m
    const int m    = hist[s_b3];     // multiplicity of threshold value
    const bool keep_all_eq = (need >= m) || (m > 512);

    // exact tie ranking (lowest indices first) — rare path
    if (tbits != 0u && !keep_all_eq) {
        for (int i = t; i < NN; i += 256)
            if (v[i] == tbits) { const int p = atomicAdd(&s_eqcnt, 1); eqix[p] = i; }
        __syncthreads();
    }

    // write masked row back
    for (int i = t; i < NN; i += 256) {
        const unsigned int u = v[i];
        float val = 0.0f;
        if (u > tbits) {
            val = __uint_as_float(u);
        } else if (u == tbits && tbits != 0u) {
            if (keep_all_eq) {
                val = __uint_as_float(u);
            } else {
                int rank = 0;
                for (int q = 0; q < m; ++q) rank += (eqix[q] < i);
                if (rank < need) val = __uint_as_float(u);
            }
        }
        rp[i] = val;
    }
}

// ---------------------------------------------------------------------------
// Launch
// ---------------------------------------------------------------------------
extern "C" void kernel_launch(void* const* d_in, const int* in_sizes, int n_in,
                              void* d_out, int out_size)
{
    // Map inputs by element count (x=1048576, W=4194304, bias=16384)
    const float* x = nullptr;
    const float* W = nullptr;
    const float* bias = nullptr;
    for (int i = 0; i < n_in; ++i) {
        if (in_sizes[i] == M_ROWS * K_DIM)      x = (const float*)d_in[i];
        else if (in_sizes[i] == K_DIM * NN)     W = (const float*)d_in[i];
        else if (in_sizes[i] == NN)             bias = (const float*)d_in[i];
    }
    float* out = (float*)d_out;

    cudaFuncSetAttribute(gemm_kernel, cudaFuncAttributeMaxDynamicSharedMemorySize, GEMM_SMEM);
    cudaFuncSetAttribute(topk_kernel, cudaFuncAttributeMaxDynamicSharedMemorySize, SEL_SMEM);

    build_csc_kernel<<<NN / 128, 128>>>(W);

    dim3 ggrid(NN / 128, M_ROWS / 128);
    gemm_kernel<<<ggrid, 256, GEMM_SMEM>>>(x, bias, out);

    topk_kernel<<<M_ROWS, 256, SEL_SMEM>>>(out);
}